// round 3
// baseline (speedup 1.0000x reference)
#include <cuda_runtime.h>
#include <cuda_fp16.h>
#include <cstdint>

// ============================================================
// Fused GRUCell, sm_103 base-PTX path (toolchain emits compute_103:
// no tcgen05 available -> ldmatrix + mma.sync HMMA.16816).
//   r = sig(x@Wir + hx@Whr + br); z = sig(x@Wiz + hx@Whz + bz)
//   n = tanh(x@Win + (r*hx)@Whn + bn); h = (1-z)*hx + z*n
// B = 1048576, H = 64. Persistent CTAs, fp16 GEMM / fp32 accum,
// fp32 hx copy for exact epilogue, r*hx fragments built in-register.
// ============================================================

#define DEV __device__ __forceinline__

static constexpr int TILE = 256;                  // rows per CTA iteration
static constexpr int NT   = 1048576 / TILE;       // 4096 tiles

// ---- dynamic SMEM layout (bytes) ----
static constexpr int OFF_W    = 0;                // 6 x [64x64] f16, SW128 rows (8192B each) = 49152
static constexpr int OFF_XT   = 49152;            // x tile f16: 256 rows x 128B = 32768
static constexpr int OFF_HT   = 81920;            // hx tile f16: 32768
static constexpr int OFF_HX   = 114688;           // hx tile fp32, padded rows: 256 x 272B = 69632
static constexpr int HXS      = 272;              // fp32 row stride (16B aligned, bank-spread)
static constexpr int OFF_BIAS = 184320;           // 3 x 64 fp32 = 768
static constexpr int SMEM_SZ  = 185344;

DEV uint32_t sw(uint32_t o) { return o ^ ((o >> 3) & 0x70); }

DEV uint32_t s2u(const void* p) {
    uint32_t a;
    asm("{ .reg .u64 t; cvta.to.shared.u64 t, %1; cvt.u32.u64 %0, t; }" : "=r"(a) : "l"(p));
    return a;
}

DEV void ldsm4(uint32_t& d0, uint32_t& d1, uint32_t& d2, uint32_t& d3, uint32_t a) {
    asm volatile("ldmatrix.sync.aligned.m8n8.x4.shared.b16 {%0,%1,%2,%3}, [%4];"
                 : "=r"(d0), "=r"(d1), "=r"(d2), "=r"(d3) : "r"(a));
}

DEV void ldsm4t(uint32_t& d0, uint32_t& d1, uint32_t& d2, uint32_t& d3, uint32_t a) {
    asm volatile("ldmatrix.sync.aligned.m8n8.x4.trans.shared.b16 {%0,%1,%2,%3}, [%4];"
                 : "=r"(d0), "=r"(d1), "=r"(d2), "=r"(d3) : "r"(a));
}

DEV void mma4(float* c, const uint32_t* a, uint32_t b0, uint32_t b1) {
    asm volatile(
        "mma.sync.aligned.m16n8k16.row.col.f32.f16.f16.f32 "
        "{%0,%1,%2,%3}, {%4,%5,%6,%7}, {%8,%9}, {%0,%1,%2,%3};"
        : "+f"(c[0]), "+f"(c[1]), "+f"(c[2]), "+f"(c[3])
        : "r"(a[0]), "r"(a[1]), "r"(a[2]), "r"(a[3]), "r"(b0), "r"(b1));
}

// accurate sigmoid / tanh (ex2 + rcp; ~1e-6 err)
DEV float sigm(float x) {
    float e, r;
    asm("ex2.approx.f32 %0, %1;" : "=f"(e) : "f"(-1.4426950408889634f * x));
    asm("rcp.approx.f32 %0, %1;" : "=f"(r) : "f"(1.0f + e));
    return r;
}
DEV float tanh_acc(float x) {
    x = fminf(fmaxf(x, -15.0f), 15.0f);
    float e, r;
    asm("ex2.approx.f32 %0, %1;" : "=f"(e) : "f"(-2.8853900817779268f * x));  // exp(-2x)
    asm("rcp.approx.f32 %0, %1;" : "=f"(r) : "f"(1.0f + e));
    return fmaf(2.0f, r, -1.0f);
}

DEV uint32_t packh2(float a, float b) {
    __half2 h = __floats2half2_rn(a, b);
    return *(uint32_t*)&h;
}

// GEMM accumulate: acc[2][8][4] += A_tile(32xK=64, from smem fp16) @ W (64x64 smem fp16)
DEV void gemm_sm(float acc[2][8][4], uint32_t abase, uint32_t wbase, int wr, int laneA) {
    #pragma unroll
    for (int kb = 0; kb < 4; kb++) {
        uint32_t af[2][4];
        #pragma unroll
        for (int mb = 0; mb < 2; mb++) {
            uint32_t o = (uint32_t)((wr + mb * 16) * 128 + laneA + kb * 32);
            ldsm4(af[mb][0], af[mb][1], af[mb][2], af[mb][3], abase + sw(o));
        }
        #pragma unroll
        for (int nbp = 0; nbp < 4; nbp++) {
            uint32_t o = (uint32_t)(laneA + kb * 2048 + nbp * 32);
            uint32_t b0, b1, b2, b3;
            ldsm4t(b0, b1, b2, b3, wbase + sw(o));
            #pragma unroll
            for (int mb = 0; mb < 2; mb++) {
                mma4(acc[mb][2 * nbp],     af[mb], b0, b1);
                mma4(acc[mb][2 * nbp + 1], af[mb], b2, b3);
            }
        }
    }
}

// GEMM accumulate with A fragments already in registers (for r*hx)
DEV void gemm_fr(float acc[2][8][4], const uint32_t af[2][4][4], uint32_t wbase, int laneA) {
    #pragma unroll
    for (int kb = 0; kb < 4; kb++) {
        #pragma unroll
        for (int nbp = 0; nbp < 4; nbp++) {
            uint32_t o = (uint32_t)(laneA + kb * 2048 + nbp * 32);
            uint32_t b0, b1, b2, b3;
            ldsm4t(b0, b1, b2, b3, wbase + sw(o));
            #pragma unroll
            for (int mb = 0; mb < 2; mb++) {
                mma4(acc[mb][2 * nbp],     af[mb][kb], b0, b1);
                mma4(acc[mb][2 * nbp + 1], af[mb][kb], b2, b3);
            }
        }
    }
}

__global__ void __launch_bounds__(256, 1) gru_kernel(
    const float* __restrict__ x,    const float* __restrict__ hx,
    const float* __restrict__ w_ir, const float* __restrict__ w_hr,
    const float* __restrict__ w_iz, const float* __restrict__ w_hz,
    const float* __restrict__ w_in, const float* __restrict__ w_hn,
    const float* __restrict__ b_r,  const float* __restrict__ b_z,
    const float* __restrict__ b_n,  float* __restrict__ out)
{
    extern __shared__ char sm[];
    const uint32_t SB = s2u(sm);
    const int tid  = threadIdx.x;
    const int lane = tid & 31;
    const int wid  = tid >> 5;

    // ---- one-time: weights -> f16 SMEM ([k][n] rows of 128B, SW128), biases ----
    {
        const float* ws[6] = {w_ir, w_hr, w_iz, w_hz, w_in, w_hn};
        #pragma unroll 1
        for (int g = 0; g < 6; g++) {
            const float* w = ws[g];
            for (int i = tid; i < 4096; i += 256) {
                int k = i >> 6, n = i & 63;
                *(__half*)(sm + OFF_W + g * 8192 + sw((uint32_t)(k * 128 + n * 2))) =
                    __float2half_rn(w[i]);
            }
        }
        if (tid < 64) {
            float* bs = (float*)(sm + OFF_BIAS);
            bs[tid]       = b_r[tid];
            bs[64 + tid]  = b_z[tid];
            bs[128 + tid] = b_n[tid];
        }
    }
    __syncthreads();

    const int laneA = (lane & 15) * 128 + ((lane >> 4) << 4);  // ldmatrix lane offset
    const int q2    = (lane & 3) * 2;                          // col pair in n-block
    const int grow  = lane >> 2;                               // row in 8-group
    const int wr    = wid * 32;                                // slab row in tile

    for (int t = blockIdx.x; t < NT; t += gridDim.x) {
        __syncthreads();   // previous iteration done reading tiles

        // ---- cooperative tile load: fp32 -> fp16 (x, hx) + fp32 hx copy ----
        {
            const float4* xs = ((const float4*)x)  + (size_t)t * 4096;
            const float4* hs = ((const float4*)hx) + (size_t)t * 4096;
            #pragma unroll
            for (int j = 0; j < 16; j++) {
                int idx = tid + j * 256;
                int row = idx >> 4, c4 = idx & 15;
                uint32_t so = sw((uint32_t)(row * 128 + c4 * 8));
                float4 v = xs[idx];
                *(uint2*)(sm + OFF_XT + so) =
                    make_uint2(packh2(v.x, v.y), packh2(v.z, v.w));
                float4 h = hs[idx];
                *(uint2*)(sm + OFF_HT + so) =
                    make_uint2(packh2(h.x, h.y), packh2(h.z, h.w));
                *(float4*)(sm + OFF_HX + row * HXS + c4 * 16) = h;
            }
        }
        __syncthreads();

        // ---- per-warp slab: 32 rows ----
        float rc[2][8][4], zc[2][8][4];
        #pragma unroll
        for (int nb = 0; nb < 8; nb++) {
            float2 br = *(float2*)(sm + OFF_BIAS       + (nb * 8 + q2) * 4);
            float2 bz = *(float2*)(sm + OFF_BIAS + 256 + (nb * 8 + q2) * 4);
            #pragma unroll
            for (int mb = 0; mb < 2; mb++) {
                rc[mb][nb][0] = br.x; rc[mb][nb][1] = br.y;
                rc[mb][nb][2] = br.x; rc[mb][nb][3] = br.y;
                zc[mb][nb][0] = bz.x; zc[mb][nb][1] = bz.y;
                zc[mb][nb][2] = bz.x; zc[mb][nb][3] = bz.y;
            }
        }
        gemm_sm(rc, SB + OFF_XT, SB + OFF_W,             wr, laneA);
        gemm_sm(rc, SB + OFF_HT, SB + OFF_W + 1 * 8192,  wr, laneA);
        gemm_sm(zc, SB + OFF_XT, SB + OFF_W + 2 * 8192,  wr, laneA);
        gemm_sm(zc, SB + OFF_HT, SB + OFF_W + 3 * 8192,  wr, laneA);

        // ---- rh = sigmoid(rc) * hx  -> A-fragments, all in registers ----
        // c-frag(nb=2k) supplies a0,a1; c-frag(nb=2k+1) supplies a2,a3 of A-frag kb=k.
        uint32_t rhf[2][4][4];
        #pragma unroll
        for (int mb = 0; mb < 2; mb++) {
            int r0 = wr + mb * 16 + grow;
            const float* h0 = (const float*)(sm + OFF_HX + r0 * HXS);
            const float* h8 = (const float*)(sm + OFF_HX + (r0 + 8) * HXS);
            #pragma unroll
            for (int kb = 0; kb < 4; kb++) {
                int c = kb * 16 + q2;
                float2 ha = *(const float2*)(h0 + c);
                float2 hb = *(const float2*)(h8 + c);
                float2 hc = *(const float2*)(h0 + c + 8);
                float2 hd = *(const float2*)(h8 + c + 8);
                const float* ce = rc[mb][2 * kb];
                const float* co = rc[mb][2 * kb + 1];
                rhf[mb][kb][0] = packh2(sigm(ce[0]) * ha.x, sigm(ce[1]) * ha.y);
                rhf[mb][kb][1] = packh2(sigm(ce[2]) * hb.x, sigm(ce[3]) * hb.y);
                rhf[mb][kb][2] = packh2(sigm(co[0]) * hc.x, sigm(co[1]) * hc.y);
                rhf[mb][kb][3] = packh2(sigm(co[2]) * hd.x, sigm(co[3]) * hd.y);
            }
        }

        // ---- n = x@Win + rh@Whn + bn ----
        float nc[2][8][4];
        #pragma unroll
        for (int nb = 0; nb < 8; nb++) {
            float2 bn = *(float2*)(sm + OFF_BIAS + 512 + (nb * 8 + q2) * 4);
            #pragma unroll
            for (int mb = 0; mb < 2; mb++) {
                nc[mb][nb][0] = bn.x; nc[mb][nb][1] = bn.y;
                nc[mb][nb][2] = bn.x; nc[mb][nb][3] = bn.y;
            }
        }
        gemm_sm(nc, SB + OFF_XT, SB + OFF_W + 4 * 8192, wr, laneA);
        gemm_fr(nc, rhf,         SB + OFF_W + 5 * 8192,     laneA);

        // ---- epilogue: h = hx + z*(n - hx), fp32 hx ----
        #pragma unroll
        for (int mb = 0; mb < 2; mb++) {
            int rl = wr + mb * 16 + grow;                  // row in tile
            size_t rg = (size_t)t * TILE + rl;             // global row
            const float* h0 = (const float*)(sm + OFF_HX + rl * HXS);
            const float* h8 = (const float*)(sm + OFF_HX + (rl + 8) * HXS);
            #pragma unroll
            for (int nb = 0; nb < 8; nb++) {
                int c = nb * 8 + q2;
                float2 ha = *(const float2*)(h0 + c);
                float2 hb = *(const float2*)(h8 + c);
                const float* zz = zc[mb][nb];
                const float* nn = nc[mb][nb];
                float z0 = sigm(zz[0]), z1 = sigm(zz[1]);
                float z2 = sigm(zz[2]), z3 = sigm(zz[3]);
                float n0 = tanh_acc(nn[0]), n1 = tanh_acc(nn[1]);
                float n2 = tanh_acc(nn[2]), n3 = tanh_acc(nn[3]);
                float2 o0 = make_float2(fmaf(z0, n0 - ha.x, ha.x),
                                        fmaf(z1, n1 - ha.y, ha.y));
                float2 o1 = make_float2(fmaf(z2, n2 - hb.x, hb.x),
                                        fmaf(z3, n3 - hb.y, hb.y));
                *(float2*)(out + rg * 64 + c)       = o0;
                *(float2*)(out + (rg + 8) * 64 + c) = o1;
            }
        }
    }
}

extern "C" void kernel_launch(void* const* d_in, const int* in_sizes, int n_in,
                              void* d_out, int out_size) {
    int sms = 0;
    cudaDeviceGetAttribute(&sms, cudaDevAttrMultiProcessorCount, 0);
    if (sms <= 0) sms = 148;
    cudaFuncSetAttribute(gru_kernel, cudaFuncAttributeMaxDynamicSharedMemorySize, SMEM_SZ);
    gru_kernel<<<sms, 256, SMEM_SZ>>>(
        (const float*)d_in[0], (const float*)d_in[1],
        (const float*)d_in[2], (const float*)d_in[3],
        (const float*)d_in[4], (const float*)d_in[5],
        (const float*)d_in[6], (const float*)d_in[7],
        (const float*)d_in[8], (const float*)d_in[9],
        (const float*)d_in[10], (float*)d_out);
}

// round 4
// speedup vs baseline: 1.3279x; 1.3279x over previous
#include <cuda_runtime.h>
#include <cuda_fp16.h>
#include <cstdint>

// ============================================================
// Fused GRUCell, sm_103 base-PTX (ldmatrix + mma.sync.m16n8k16).
// cp.async double-buffered fp32 staging; A-fragments built
// in-register from fp32 SMEM; weights fp16 in SMEM (one-time).
//   r = sig(x@Wir + hx@Whr + br); z = sig(x@Wiz + hx@Whz + bz)
//   n = tanh(x@Win + (r*hx)@Whn + bn); h = hx + z*(n - hx)
// B = 1048576, H = 64.
// ============================================================

#define DEV __device__ __forceinline__

static constexpr int TILE = 128;                 // rows per CTA iteration
static constexpr int NT   = 1048576 / TILE;      // 8192 tiles

// ---- dynamic SMEM layout (bytes) ----
static constexpr int OFF_W    = 0;               // 6 x [64x64] f16 SW128 rows = 49152
static constexpr int OFF_BIAS = 49152;           // 3 x 64 fp32 = 768 (pad to 1024)
static constexpr int OFF_STG  = 50176;           // 2 stages x (x + hx) fp32
static constexpr int ROWB     = 272;             // padded fp32 row stride (68 floats)
static constexpr int ARR_SZ   = TILE * ROWB;     // 34816 per array
static constexpr int STAGE_SZ = 2 * ARR_SZ;      // 69632 per stage (x then hx)
static constexpr int SMEM_SZ  = OFF_STG + 2 * STAGE_SZ;   // 189440

DEV uint32_t sw(uint32_t o) { return o ^ ((o >> 3) & 0x70); }

DEV uint32_t s2u(const void* p) {
    uint32_t a;
    asm("{ .reg .u64 t; cvta.to.shared.u64 t, %1; cvt.u32.u64 %0, t; }" : "=r"(a) : "l"(p));
    return a;
}

DEV void cp16(uint32_t dst, const void* src) {
    asm volatile("cp.async.cg.shared.global [%0], [%1], 16;" :: "r"(dst), "l"(src));
}
#define CP_COMMIT() asm volatile("cp.async.commit_group;" ::: "memory")
#define CP_WAIT1()  asm volatile("cp.async.wait_group 1;" ::: "memory")

DEV void ldsm4t(uint32_t& d0, uint32_t& d1, uint32_t& d2, uint32_t& d3, uint32_t a) {
    asm volatile("ldmatrix.sync.aligned.m8n8.x4.trans.shared.b16 {%0,%1,%2,%3}, [%4];"
                 : "=r"(d0), "=r"(d1), "=r"(d2), "=r"(d3) : "r"(a));
}

DEV void mma4(float* c, const uint32_t* a, uint32_t b0, uint32_t b1) {
    asm volatile(
        "mma.sync.aligned.m16n8k16.row.col.f32.f16.f16.f32 "
        "{%0,%1,%2,%3}, {%4,%5,%6,%7}, {%8,%9}, {%0,%1,%2,%3};"
        : "+f"(c[0]), "+f"(c[1]), "+f"(c[2]), "+f"(c[3])
        : "r"(a[0]), "r"(a[1]), "r"(a[2]), "r"(a[3]), "r"(b0), "r"(b1));
}

DEV float sigm(float x) {
    float e, r;
    asm("ex2.approx.f32 %0, %1;" : "=f"(e) : "f"(-1.4426950408889634f * x));
    asm("rcp.approx.f32 %0, %1;" : "=f"(r) : "f"(1.0f + e));
    return r;
}
DEV float tanh_acc(float x) {
    x = fminf(fmaxf(x, -15.0f), 15.0f);
    float e, r;
    asm("ex2.approx.f32 %0, %1;" : "=f"(e) : "f"(-2.8853900817779268f * x));  // exp(-2x)
    asm("rcp.approx.f32 %0, %1;" : "=f"(r) : "f"(1.0f + e));
    return fmaf(2.0f, r, -1.0f);
}

DEV uint32_t packh2(float a, float b) {
    __half2 h = __floats2half2_rn(a, b);
    return *(uint32_t*)&h;
}

// GEMM accumulate: acc[8][4] += A(16x64, register frags) @ W(64x64 f16 smem)
DEV void gemm_fr(float acc[8][4], const uint32_t af[4][4], uint32_t wbase, int laneA) {
    #pragma unroll
    for (int kb = 0; kb < 4; kb++) {
        #pragma unroll
        for (int nbp = 0; nbp < 4; nbp++) {
            uint32_t o = (uint32_t)(laneA + kb * 2048 + nbp * 32);
            uint32_t b0, b1, b2, b3;
            ldsm4t(b0, b1, b2, b3, wbase + sw(o));
            mma4(acc[2 * nbp],     af[kb], b0, b1);
            mma4(acc[2 * nbp + 1], af[kb], b2, b3);
        }
    }
}

// Build m16k16 A-fragments (4 of them, K=64) from an fp32 SMEM tile.
// Fragment layout (lane = 4*grow + tig, q2 = 2*tig):
//   a0:(grow,  q2..q2+1)  a1:(grow+8, q2..)  a2:(grow, q2+8..)  a3:(grow+8, q2+8..)
DEV void build_af(uint32_t af[4][4], const char* arr, int base, int grow, int q2) {
    const char* r0 = arr + (base + grow) * ROWB;
    const char* r8 = arr + (base + 8 + grow) * ROWB;
    #pragma unroll
    for (int kb = 0; kb < 4; kb++) {
        int c = kb * 16 + q2;
        float2 a = *(const float2*)(r0 + c * 4);
        float2 b = *(const float2*)(r8 + c * 4);
        float2 cc = *(const float2*)(r0 + (c + 8) * 4);
        float2 d = *(const float2*)(r8 + (c + 8) * 4);
        af[kb][0] = packh2(a.x, a.y);
        af[kb][1] = packh2(b.x, b.y);
        af[kb][2] = packh2(cc.x, cc.y);
        af[kb][3] = packh2(d.x, d.y);
    }
}

// Issue cp.async loads for one tile into stage s (always commits a group).
DEV void issue_tile(const float* x, const float* hx, uint32_t SB, int s, int t, int tid) {
    if (t < NT) {
        const float4* xs = ((const float4*)x)  + (size_t)t * (TILE * 16);
        const float4* hs = ((const float4*)hx) + (size_t)t * (TILE * 16);
        uint32_t xb = SB + OFF_STG + s * STAGE_SZ;
        uint32_t hb = xb + ARR_SZ;
        #pragma unroll
        for (int j = 0; j < 8; j++) {
            int idx = tid + j * 256;              // 0..2047 float4 chunks
            int row = idx >> 4, c4 = idx & 15;
            uint32_t so = (uint32_t)(row * ROWB + c4 * 16);
            cp16(xb + so, xs + idx);
            cp16(hb + so, hs + idx);
        }
    }
    CP_COMMIT();
}

__global__ void __launch_bounds__(256, 1) gru_kernel(
    const float* __restrict__ x,    const float* __restrict__ hx,
    const float* __restrict__ w_ir, const float* __restrict__ w_hr,
    const float* __restrict__ w_iz, const float* __restrict__ w_hz,
    const float* __restrict__ w_in, const float* __restrict__ w_hn,
    const float* __restrict__ b_r,  const float* __restrict__ b_z,
    const float* __restrict__ b_n,  float* __restrict__ out)
{
    extern __shared__ char sm[];
    const uint32_t SB = s2u(sm);
    const int tid  = threadIdx.x;
    const int lane = tid & 31;
    const int wid  = tid >> 5;

    // ---- one-time: weights -> f16 SMEM ([k][n] rows of 128B, SW128), biases ----
    {
        const float* ws[6] = {w_ir, w_hr, w_iz, w_hz, w_in, w_hn};
        #pragma unroll 1
        for (int g = 0; g < 6; g++) {
            const float* w = ws[g];
            for (int i = tid; i < 4096; i += 256) {
                int k = i >> 6, n = i & 63;
                *(__half*)(sm + OFF_W + g * 8192 + sw((uint32_t)(k * 128 + n * 2))) =
                    __float2half_rn(w[i]);
            }
        }
        if (tid < 64) {
            float* bs = (float*)(sm + OFF_BIAS);
            bs[tid]       = b_r[tid];
            bs[64 + tid]  = b_z[tid];
            bs[128 + tid] = b_n[tid];
        }
    }
    __syncthreads();

    const int laneA = (lane & 15) * 128 + ((lane >> 4) << 4);  // ldmatrix lane offset (B)
    const int q2    = (lane & 3) * 2;
    const int grow  = lane >> 2;
    const int base  = wid * 16;                                // warp's rows in tile

    // ---- pipeline prologue: stage 0 <- tile t0, stage 1 <- tile t1 ----
    issue_tile(x, hx, SB, 0, blockIdx.x, tid);
    issue_tile(x, hx, SB, 1, blockIdx.x + gridDim.x, tid);

    int i = 0;
    for (int t = blockIdx.x; t < NT; t += gridDim.x, i++) {
        const int s = i & 1;
        const char* xa = sm + OFF_STG + s * STAGE_SZ;
        const char* ha = xa + ARR_SZ;

        CP_WAIT1();            // stage s data arrived
        __syncthreads();

        // ---- A fragments from fp32 staging ----
        uint32_t xf[4][4], hf[4][4];
        build_af(xf, xa, base, grow, q2);
        build_af(hf, ha, base, grow, q2);

        // ---- r, z accumulators (bias-initialized) ----
        float rc[8][4], zc[8][4];
        #pragma unroll
        for (int nb = 0; nb < 8; nb++) {
            float2 br = *(float2*)(sm + OFF_BIAS       + (nb * 8 + q2) * 4);
            float2 bz = *(float2*)(sm + OFF_BIAS + 256 + (nb * 8 + q2) * 4);
            rc[nb][0] = br.x; rc[nb][1] = br.y; rc[nb][2] = br.x; rc[nb][3] = br.y;
            zc[nb][0] = bz.x; zc[nb][1] = bz.y; zc[nb][2] = bz.x; zc[nb][3] = bz.y;
        }
        gemm_fr(rc, xf, SB + OFF_W,            laneA);
        gemm_fr(rc, hf, SB + OFF_W + 1 * 8192, laneA);
        gemm_fr(zc, xf, SB + OFF_W + 2 * 8192, laneA);
        gemm_fr(zc, hf, SB + OFF_W + 3 * 8192, laneA);

        // ---- rh = sigmoid(rc) * hx -> A-fragments in registers ----
        // c-frag(nb=2k) -> a0,a1 ; c-frag(nb=2k+1) -> a2,a3 of A-frag kb=k.
        uint32_t rhf[4][4];
        {
            const char* r0 = ha + (base + grow) * ROWB;
            const char* r8 = ha + (base + 8 + grow) * ROWB;
            #pragma unroll
            for (int kb = 0; kb < 4; kb++) {
                int c = kb * 16 + q2;
                float2 a  = *(const float2*)(r0 + c * 4);
                float2 b  = *(const float2*)(r8 + c * 4);
                float2 cc = *(const float2*)(r0 + (c + 8) * 4);
                float2 d  = *(const float2*)(r8 + (c + 8) * 4);
                const float* ce = rc[2 * kb];
                const float* co = rc[2 * kb + 1];
                rhf[kb][0] = packh2(sigm(ce[0]) * a.x,  sigm(ce[1]) * a.y);
                rhf[kb][1] = packh2(sigm(ce[2]) * b.x,  sigm(ce[3]) * b.y);
                rhf[kb][2] = packh2(sigm(co[0]) * cc.x, sigm(co[1]) * cc.y);
                rhf[kb][3] = packh2(sigm(co[2]) * d.x,  sigm(co[3]) * d.y);
            }
        }

        // ---- n = x@Win + rh@Whn + bn ----
        float nc[8][4];
        #pragma unroll
        for (int nb = 0; nb < 8; nb++) {
            float2 bn = *(float2*)(sm + OFF_BIAS + 512 + (nb * 8 + q2) * 4);
            nc[nb][0] = bn.x; nc[nb][1] = bn.y; nc[nb][2] = bn.x; nc[nb][3] = bn.y;
        }
        gemm_fr(nc, xf,  SB + OFF_W + 4 * 8192, laneA);
        gemm_fr(nc, rhf, SB + OFF_W + 5 * 8192, laneA);

        // ---- epilogue: h = hx + z*(n - hx) (fp32 hx from staging) ----
        {
            int rl = base + grow;
            size_t rg = (size_t)t * TILE + rl;
            const float* h0 = (const float*)(ha + rl * ROWB);
            const float* h8 = (const float*)(ha + (rl + 8) * ROWB);
            #pragma unroll
            for (int nb = 0; nb < 8; nb++) {
                int c = nb * 8 + q2;
                float2 a = *(const float2*)(h0 + c);
                float2 b = *(const float2*)(h8 + c);
                const float* zz = zc[nb];
                const float* nn = nc[nb];
                float z0 = sigm(zz[0]), z1 = sigm(zz[1]);
                float z2 = sigm(zz[2]), z3 = sigm(zz[3]);
                float n0 = tanh_acc(nn[0]), n1 = tanh_acc(nn[1]);
                float n2 = tanh_acc(nn[2]), n3 = tanh_acc(nn[3]);
                *(float2*)(out + rg * 64 + c) =
                    make_float2(fmaf(z0, n0 - a.x, a.x), fmaf(z1, n1 - a.y, a.y));
                *(float2*)(out + (rg + 8) * 64 + c) =
                    make_float2(fmaf(z2, n2 - b.x, b.x), fmaf(z3, n3 - b.y, b.y));
            }
        }

        __syncthreads();       // all warps done reading stage s
        issue_tile(x, hx, SB, s, t + 2 * gridDim.x, tid);   // refill stage s
    }
}

extern "C" void kernel_launch(void* const* d_in, const int* in_sizes, int n_in,
                              void* d_out, int out_size) {
    int sms = 0;
    cudaDeviceGetAttribute(&sms, cudaDevAttrMultiProcessorCount, 0);
    if (sms <= 0) sms = 148;
    cudaFuncSetAttribute(gru_kernel, cudaFuncAttributeMaxDynamicSharedMemorySize, SMEM_SZ);
    gru_kernel<<<sms, 256, SMEM_SZ>>>(
        (const float*)d_in[0], (const float*)d_in[1],
        (const float*)d_in[2], (const float*)d_in[3],
        (const float*)d_in[4], (const float*)d_in[5],
        (const float*)d_in[6], (const float*)d_in[7],
        (const float*)d_in[8], (const float*)d_in[9],
        (const float*)d_in[10], (float*)d_out);
}

// round 5
// speedup vs baseline: 1.6717x; 1.2589x over previous
#include <cuda_runtime.h>
#include <cuda_fp16.h>
#include <cstdint>

// ============================================================
// Fused GRUCell, sm_103 base-PTX (ldmatrix + mma.sync.m16n8k16).
// Warp-autonomous 16-row slabs, per-warp cp.async double-buffered
// fp32 staging, NO inter-warp barriers in the main loop.
//   r = sig(x@Wir + hx@Whr + br); z = sig(x@Wiz + hx@Whz + bz)
//   n = tanh(x@Win + (r*hx)@Whn + bn); h = hx + z*(n - hx)
// B = 1048576, H = 64. Single-MUFU activations (tanh.approx).
// ============================================================

#define DEV __device__ __forceinline__

static constexpr int NS = 1048576 / 16;          // 65536 slabs of 16 rows

// ---- dynamic SMEM layout (bytes) ----
static constexpr int OFF_W    = 0;               // 6 x [64x64] f16 SW128 rows = 49152
static constexpr int OFF_BIAS = 49152;           // 3 x 64 fp32 = 768 (pad to 1024)
static constexpr int OFF_STG  = 50176;           // per-warp staging
static constexpr int ROWB     = 272;             // padded fp32 row stride
static constexpr int ARR_SZ   = 16 * ROWB;       // 4352 per 16-row array
static constexpr int STAGE_SZ = 2 * ARR_SZ;      // 8704 (x then hx)
static constexpr int WARP_STG = 2 * STAGE_SZ;    // 17408 (2 stages)
static constexpr int SMEM_SZ  = OFF_STG + 8 * WARP_STG;   // 189440

DEV uint32_t sw(uint32_t o) { return o ^ ((o >> 3) & 0x70); }

DEV uint32_t s2u(const void* p) {
    uint32_t a;
    asm("{ .reg .u64 t; cvta.to.shared.u64 t, %1; cvt.u32.u64 %0, t; }" : "=r"(a) : "l"(p));
    return a;
}

DEV void cp16(uint32_t dst, const void* src) {
    asm volatile("cp.async.cg.shared.global [%0], [%1], 16;" :: "r"(dst), "l"(src));
}
#define CP_COMMIT() asm volatile("cp.async.commit_group;" ::: "memory")
#define CP_WAIT1()  asm volatile("cp.async.wait_group 1;" ::: "memory")

DEV void ldsm4t(uint32_t& d0, uint32_t& d1, uint32_t& d2, uint32_t& d3, uint32_t a) {
    asm volatile("ldmatrix.sync.aligned.m8n8.x4.trans.shared.b16 {%0,%1,%2,%3}, [%4];"
                 : "=r"(d0), "=r"(d1), "=r"(d2), "=r"(d3) : "r"(a));
}

DEV void mma4(float* c, const uint32_t* a, uint32_t b0, uint32_t b1) {
    asm volatile(
        "mma.sync.aligned.m16n8k16.row.col.f32.f16.f16.f32 "
        "{%0,%1,%2,%3}, {%4,%5,%6,%7}, {%8,%9}, {%0,%1,%2,%3};"
        : "+f"(c[0]), "+f"(c[1]), "+f"(c[2]), "+f"(c[3])
        : "r"(a[0]), "r"(a[1]), "r"(a[2]), "r"(a[3]), "r"(b0), "r"(b1));
}

// single-MUFU activations
DEV float tanh_ap(float x) {
    float r;
    asm("tanh.approx.f32 %0, %1;" : "=f"(r) : "f"(x));
    return r;
}
DEV float sigm(float x) { return fmaf(0.5f, tanh_ap(0.5f * x), 0.5f); }

DEV uint32_t packh2(float a, float b) {
    __half2 h = __floats2half2_rn(a, b);
    return *(uint32_t*)&h;
}

// GEMM accumulate: acc[8][4] += A(16x64, register frags) @ W(64x64 f16 smem)
DEV void gemm_fr(float acc[8][4], const uint32_t af[4][4], uint32_t wbase, int laneA) {
    #pragma unroll
    for (int kb = 0; kb < 4; kb++) {
        #pragma unroll
        for (int nbp = 0; nbp < 4; nbp++) {
            uint32_t o = (uint32_t)(laneA + kb * 2048 + nbp * 32);
            uint32_t b0, b1, b2, b3;
            ldsm4t(b0, b1, b2, b3, wbase + sw(o));
            mma4(acc[2 * nbp],     af[kb], b0, b1);
            mma4(acc[2 * nbp + 1], af[kb], b2, b3);
        }
    }
}

// Build m16k16 A-fragments (4, K=64) from an fp32 SMEM 16-row array.
DEV void build_af(uint32_t af[4][4], const char* arr, int grow, int q2) {
    const char* r0 = arr + grow * ROWB;
    const char* r8 = arr + (8 + grow) * ROWB;
    #pragma unroll
    for (int kb = 0; kb < 4; kb++) {
        int c = kb * 16 + q2;
        float2 a  = *(const float2*)(r0 + c * 4);
        float2 b  = *(const float2*)(r8 + c * 4);
        float2 cc = *(const float2*)(r0 + (c + 8) * 4);
        float2 d  = *(const float2*)(r8 + (c + 8) * 4);
        af[kb][0] = packh2(a.x, a.y);
        af[kb][1] = packh2(b.x, b.y);
        af[kb][2] = packh2(cc.x, cc.y);
        af[kb][3] = packh2(d.x, d.y);
    }
}

// Per-warp: issue cp.async for one 16-row slab into stage s (always commits).
DEV void issue_slab(const float* x, const float* hx, uint32_t wstg, int s, int t, int lane) {
    if (t < NS) {
        const float4* xs = ((const float4*)x)  + (size_t)t * 256;   // 16 rows x 16 float4
        const float4* hs = ((const float4*)hx) + (size_t)t * 256;
        uint32_t xb = wstg + (uint32_t)s * STAGE_SZ;
        uint32_t hb = xb + ARR_SZ;
        #pragma unroll
        for (int j = 0; j < 8; j++) {
            int idx = lane + j * 32;            // 0..255 float4 chunks
            int row = idx >> 4, c4 = idx & 15;
            uint32_t so = (uint32_t)(row * ROWB + c4 * 16);
            cp16(xb + so, xs + idx);
            cp16(hb + so, hs + idx);
        }
    }
    CP_COMMIT();
}

__global__ void __launch_bounds__(256, 1) gru_kernel(
    const float* __restrict__ x,    const float* __restrict__ hx,
    const float* __restrict__ w_ir, const float* __restrict__ w_hr,
    const float* __restrict__ w_iz, const float* __restrict__ w_hz,
    const float* __restrict__ w_in, const float* __restrict__ w_hn,
    const float* __restrict__ b_r,  const float* __restrict__ b_z,
    const float* __restrict__ b_n,  float* __restrict__ out)
{
    extern __shared__ char sm[];
    const uint32_t SB = s2u(sm);
    const int tid  = threadIdx.x;
    const int lane = tid & 31;
    const int wid  = tid >> 5;

    // ---- one-time: weights -> f16 SMEM ([k][n] rows of 128B, SW128), biases ----
    {
        const float* ws[6] = {w_ir, w_hr, w_iz, w_hz, w_in, w_hn};
        #pragma unroll 1
        for (int g = 0; g < 6; g++) {
            const float* w = ws[g];
            for (int i = tid; i < 4096; i += 256) {
                int k = i >> 6, n = i & 63;
                *(__half*)(sm + OFF_W + g * 8192 + sw((uint32_t)(k * 128 + n * 2))) =
                    __float2half_rn(w[i]);
            }
        }
        if (tid < 64) {
            float* bs = (float*)(sm + OFF_BIAS);
            bs[tid]       = b_r[tid];
            bs[64 + tid]  = b_z[tid];
            bs[128 + tid] = b_n[tid];
        }
    }
    __syncthreads();   // only CTA-wide barrier in the kernel

    const int laneA = (lane & 15) * 128 + ((lane >> 4) << 4);  // ldmatrix B lane offset
    const int q2    = (lane & 3) * 2;
    const int grow  = lane >> 2;
    const uint32_t wstg = SB + OFF_STG + (uint32_t)wid * WARP_STG;
    const char*    wstg_c = sm + OFF_STG + wid * WARP_STG;

    const int wg     = blockIdx.x * 8 + wid;     // global warp id
    const int stride = gridDim.x * 8;

    // ---- prologue: fill both stages ----
    issue_slab(x, hx, wstg, 0, wg, lane);
    issue_slab(x, hx, wstg, 1, wg + stride, lane);

    int i = 0;
    for (int t = wg; t < NS; t += stride, i++) {
        const int s = i & 1;
        const char* xa = wstg_c + s * STAGE_SZ;
        const char* ha = xa + ARR_SZ;

        CP_WAIT1();
        __syncwarp();

        // ---- A fragments from fp32 staging ----
        uint32_t xf[4][4], hf[4][4];
        build_af(xf, xa, grow, q2);
        build_af(hf, ha, grow, q2);

        // ---- r, z (bias-initialized accumulators) ----
        float rc[8][4], zc[8][4];
        #pragma unroll
        for (int nb = 0; nb < 8; nb++) {
            float2 br = *(float2*)(sm + OFF_BIAS       + (nb * 8 + q2) * 4);
            float2 bz = *(float2*)(sm + OFF_BIAS + 256 + (nb * 8 + q2) * 4);
            rc[nb][0] = br.x; rc[nb][1] = br.y; rc[nb][2] = br.x; rc[nb][3] = br.y;
            zc[nb][0] = bz.x; zc[nb][1] = bz.y; zc[nb][2] = bz.x; zc[nb][3] = bz.y;
        }
        gemm_fr(rc, xf, SB + OFF_W,            laneA);
        gemm_fr(rc, hf, SB + OFF_W + 1 * 8192, laneA);
        gemm_fr(zc, xf, SB + OFF_W + 2 * 8192, laneA);
        gemm_fr(zc, hf, SB + OFF_W + 3 * 8192, laneA);

        // ---- rh = sigmoid(rc) * hx -> A-fragments in registers ----
        uint32_t rhf[4][4];
        {
            const char* r0 = ha + grow * ROWB;
            const char* r8 = ha + (8 + grow) * ROWB;
            #pragma unroll
            for (int kb = 0; kb < 4; kb++) {
                int c = kb * 16 + q2;
                float2 a  = *(const float2*)(r0 + c * 4);
                float2 b  = *(const float2*)(r8 + c * 4);
                float2 cc = *(const float2*)(r0 + (c + 8) * 4);
                float2 d  = *(const float2*)(r8 + (c + 8) * 4);
                const float* ce = rc[2 * kb];
                const float* co = rc[2 * kb + 1];
                rhf[kb][0] = packh2(sigm(ce[0]) * a.x,  sigm(ce[1]) * a.y);
                rhf[kb][1] = packh2(sigm(ce[2]) * b.x,  sigm(ce[3]) * b.y);
                rhf[kb][2] = packh2(sigm(co[0]) * cc.x, sigm(co[1]) * cc.y);
                rhf[kb][3] = packh2(sigm(co[2]) * d.x,  sigm(co[3]) * d.y);
            }
        }

        // ---- n = x@Win + rh@Whn + bn ----
        float nc[8][4];
        #pragma unroll
        for (int nb = 0; nb < 8; nb++) {
            float2 bn = *(float2*)(sm + OFF_BIAS + 512 + (nb * 8 + q2) * 4);
            nc[nb][0] = bn.x; nc[nb][1] = bn.y; nc[nb][2] = bn.x; nc[nb][3] = bn.y;
        }
        gemm_fr(nc, xf,  SB + OFF_W + 4 * 8192, laneA);
        gemm_fr(nc, rhf, SB + OFF_W + 5 * 8192, laneA);

        // ---- epilogue: h = hx + z*(n - hx), fp32 hx from staging ----
        {
            size_t rg = (size_t)t * 16 + grow;
            const float* h0 = (const float*)(ha + grow * ROWB);
            const float* h8 = (const float*)(ha + (8 + grow) * ROWB);
            #pragma unroll
            for (int nb = 0; nb < 8; nb++) {
                int c = nb * 8 + q2;
                float2 a = *(const float2*)(h0 + c);
                float2 b = *(const float2*)(h8 + c);
                const float* zz = zc[nb];
                const float* nn = nc[nb];
                float z0 = sigm(zz[0]), z1 = sigm(zz[1]);
                float z2 = sigm(zz[2]), z3 = sigm(zz[3]);
                float n0 = tanh_ap(nn[0]), n1 = tanh_ap(nn[1]);
                float n2 = tanh_ap(nn[2]), n3 = tanh_ap(nn[3]);
                *(float2*)(out + rg * 64 + c) =
                    make_float2(fmaf(z0, n0 - a.x, a.x), fmaf(z1, n1 - a.y, a.y));
                *(float2*)(out + (rg + 8) * 64 + c) =
                    make_float2(fmaf(z2, n2 - b.x, b.x), fmaf(z3, n3 - b.y, b.y));
            }
        }

        __syncwarp();                              // warp done reading stage s
        issue_slab(x, hx, wstg, s, t + 2 * stride, lane);   // refill stage s
    }
}

extern "C" void kernel_launch(void* const* d_in, const int* in_sizes, int n_in,
                              void* d_out, int out_size) {
    int sms = 0;
    cudaDeviceGetAttribute(&sms, cudaDevAttrMultiProcessorCount, 0);
    if (sms <= 0) sms = 148;
    cudaFuncSetAttribute(gru_kernel, cudaFuncAttributeMaxDynamicSharedMemorySize, SMEM_SZ);
    gru_kernel<<<sms, 256, SMEM_SZ>>>(
        (const float*)d_in[0], (const float*)d_in[1],
        (const float*)d_in[2], (const float*)d_in[3],
        (const float*)d_in[4], (const float*)d_in[5],
        (const float*)d_in[6], (const float*)d_in[7],
        (const float*)d_in[8], (const float*)d_in[9],
        (const float*)d_in[10], (float*)d_out);
}